// round 11
// baseline (speedup 1.0000x reference)
#include <cuda_runtime.h>
#include <cuda_bf16.h>
#include <math.h>
#include <stdint.h>

// Problem dims
#define TT   512
#define BB   64
#define INPS 256
#define HH   512

// Kernel config: per cell 16 j-pairs x 2 batch-halves = 32 CTAs; 4 cells = 128
#define NCTA 128
#define JT   32       // j rows per CTA (2 x 16-row tiles)
#define BT   32       // batch cols per CTA
#define KC   256      // K rows per chunk

// Smem layout
#define VROWB        80                     // staged k-row stride: 64B data + 16B pad
#define VPLANE_BYTES (KC * VROWB)           // 20480
#define VBUF_BYTES   (2 * VPLANE_BYTES)     // 40960 (hi+lo planes)
#define RS           36                     // reduction row stride (floats)
#define RED_BYTES    (8 * JT * RS * 4)      // 36864
#define SMEM_TOTAL   (4 * VBUF_BYTES + RED_BYTES)   // 200704

// ---------------- device scratch ---------------------------------------------
__device__ __align__(256) uint16_t g_WA[4][32][64][2][256];
__device__ __align__(256) float    g_bias[4][HH];
__device__ __align__(256) uint16_t g_x2[2][TT][INPS][BB];   // x bf16 hi/lo planes [p][t][i][b]
__device__ __align__(256) uint16_t g_h2[4][2][2][HH][BB];   // state [cell][parity][plane][j][b]
__device__ __align__(256) unsigned g_flag[2][64];           // per-btile CTA step flags

struct Params { const float* p[20]; };

// ---------------- helpers -----------------------------------------------------
__device__ __forceinline__ uint32_t s2u(const void* p) {
    uint32_t a;
    asm("{ .reg .u64 t; cvta.to.shared.u64 t, %1; cvt.u32.u64 %0, t; }"
        : "=r"(a) : "l"(p));
    return a;
}

__device__ __forceinline__ void ldsm_x4(uint32_t& r0, uint32_t& r1,
                                        uint32_t& r2, uint32_t& r3, uint32_t addr) {
    asm volatile("ldmatrix.sync.aligned.m8n8.x4.shared.b16 {%0,%1,%2,%3}, [%4];"
                 : "=r"(r0), "=r"(r1), "=r"(r2), "=r"(r3) : "r"(addr));
}

__device__ __forceinline__ void ldsm_x4t(uint32_t& r0, uint32_t& r1,
                                         uint32_t& r2, uint32_t& r3, uint32_t addr) {
    asm volatile("ldmatrix.sync.aligned.m8n8.x4.trans.shared.b16 {%0,%1,%2,%3}, [%4];"
                 : "=r"(r0), "=r"(r1), "=r"(r2), "=r"(r3) : "r"(addr));
}

__device__ __forceinline__ void mma_bf16(float* c,
                                         uint32_t a0, uint32_t a1, uint32_t a2, uint32_t a3,
                                         uint32_t b0, uint32_t b1) {
    asm volatile("mma.sync.aligned.m16n8k16.row.col.f32.bf16.bf16.f32 "
                 "{%0,%1,%2,%3}, {%4,%5,%6,%7}, {%8,%9}, {%0,%1,%2,%3};"
                 : "+f"(c[0]), "+f"(c[1]), "+f"(c[2]), "+f"(c[3])
                 : "r"(a0), "r"(a1), "r"(a2), "r"(a3), "r"(b0), "r"(b1));
}

__device__ __forceinline__ void cp_async16(uint32_t dst, const void* src) {
    asm volatile("cp.async.cg.shared.global [%0], [%1], 16;" :: "r"(dst), "l"(src));
}
__device__ __forceinline__ void cp_commit() { asm volatile("cp.async.commit_group;"); }
__device__ __forceinline__ void cp_wait_n(int n) {
    switch (n) {
    case 0: asm volatile("cp.async.wait_group 0;" ::: "memory"); break;
    case 1: asm volatile("cp.async.wait_group 1;" ::: "memory"); break;
    case 2: asm volatile("cp.async.wait_group 2;" ::: "memory"); break;
    default: asm volatile("cp.async.wait_group 3;" ::: "memory"); break;
    }
}

__device__ __forceinline__ uint32_t pack_split(float x, float y, uint32_t& lopack) {
    __nv_bfloat16 hx = __float2bfloat16(x), hy = __float2bfloat16(y);
    __nv_bfloat16 lx = __float2bfloat16(x - __bfloat162float(hx));
    __nv_bfloat16 ly = __float2bfloat16(y - __bfloat162float(hy));
    lopack = (uint32_t)__bfloat16_as_ushort(lx) | ((uint32_t)__bfloat16_as_ushort(ly) << 16);
    return (uint32_t)__bfloat16_as_ushort(hx) | ((uint32_t)__bfloat16_as_ushort(hy) << 16);
}

// ---------------- init: zero states + flags -----------------------------------
__global__ void init_kernel() {
    int idx = blockIdx.x * blockDim.x + threadIdx.x;
    int stride = gridDim.x * blockDim.x;
    uint32_t* h = (uint32_t*)&g_h2[0][0][0][0][0];
    const int n = (int)(sizeof(g_h2) / 4);
    for (int i = idx; i < n; i += stride) h[i] = 0u;
    if (idx < 128) ((unsigned*)g_flag)[idx] = 0u;
}

// ---------------- prep: split + tile weights, combine biases ------------------
__device__ __forceinline__ void put_w(int c, int j, int k, float w) {
    int jt = j >> 4, jl = j & 15, kc = k >> 4, kk = k & 15;
    int t = (jl >> 3) | ((kk >> 3) << 1);
    int off = t * 64 + (jl & 7) * 8 + (kk & 7);
    __nv_bfloat16 hi = __float2bfloat16(w);
    __nv_bfloat16 lo = __float2bfloat16(w - __bfloat162float(hi));
    g_WA[c][jt][kc][0][off] = __bfloat16_as_ushort(hi);
    g_WA[c][jt][kc][1][off] = __bfloat16_as_ushort(lo);
}

__global__ void prep_kernel(Params P) {
    int idx = blockIdx.x * blockDim.x + threadIdx.x;
    int stride = gridDim.x * blockDim.x;

    for (int i = idx; i < HH * INPS; i += stride) {
        int j = i / INPS, k = i - j * INPS;
        put_w(0, j, k, P.p[1][i]);
    }
    for (int i = idx; i < HH * HH; i += stride) {
        int j = i / HH, k = i - j * HH;
        put_w(0, j, INPS + k, P.p[3][i]);
    }
    const int ihI[3] = {5, 10, 15};
    const int mI[3]  = {6, 11, 16};
    const int hhI[3] = {8, 13, 18};
    for (int c = 0; c < 3; ++c) {
        const float* wih = P.p[ihI[c]];
        const float* msk = P.p[mI[c]];
        const float* whh = P.p[hhI[c]];
        for (int i = idx; i < HH * HH; i += stride) {
            int j = i / HH, k = i - j * HH;
            put_w(c + 1, j, k, wih[i] * msk[i]);
            put_w(c + 1, j, HH + k, whh[i]);
        }
    }
    const int bihI[4] = {2, 7, 12, 17};
    const int bhhI[4] = {4, 9, 14, 19};
    for (int i = idx; i < 4 * HH; i += stride) {
        int c = i / HH, j = i - c * HH;
        g_bias[c][j] = P.p[bihI[c]][j] + P.p[bhhI[c]][j];
    }
}

// ---------------- x convert: [t][b][i] fp32 -> hi/lo planes [p][t][i][b] -----
__global__ void xconv_kernel(const float* __restrict__ x) {
    int idx = blockIdx.x * blockDim.x + threadIdx.x;
    int stride = gridDim.x * blockDim.x;
    const int n = TT * INPS * BB;
    for (int e = idx; e < n; e += stride) {
        int t = e / (INPS * BB);
        int r = e - t * (INPS * BB);
        int i = r / BB, b = r - i * BB;
        float f = x[(t * BB + b) * INPS + i];
        __nv_bfloat16 hi = __float2bfloat16(f);
        __nv_bfloat16 lo = __float2bfloat16(f - __bfloat162float(hi));
        g_x2[0][t][i][b] = __bfloat16_as_ushort(hi);
        g_x2[1][t][i][b] = __bfloat16_as_ushort(lo);
    }
}

// ---------------- chunk staging via cp.async (batch slice of 32) -------------
__device__ __forceinline__ void issue_chunk(uint32_t vdst, int cell, int c, int t,
                                            int par, int srccell, int b0c, int tid) {
#pragma unroll
    for (int p = 0; p < 2; ++p) {
        const uint16_t* s;
        if (cell == 0)
            s = (c == 0) ? &g_x2[p][t][0][b0c]
                         : &g_h2[0][par][p][(c - 1) * KC][b0c];
        else
            s = (c < 2) ? &g_h2[srccell][par][p][c * KC][b0c]
                        : &g_h2[cell][par][p][(c - 2) * KC][b0c];
        const char* sb = (const char*)s;
        const uint32_t d = vdst + p * VPLANE_BYTES;
#pragma unroll
        for (int i = 0; i < 4; ++i) {
            const int e = i * 256 + tid;        // 0..1023: row = e>>2, seg = e&3
            cp_async16(d + (uint32_t)(e >> 2) * (uint32_t)VROWB + (uint32_t)(e & 3) * 16u,
                       sb + (size_t)(e >> 2) * (BB * 2) + (size_t)(e & 3) * 16);
        }
    }
}

// ---------------- persistent pipelined recurrence -----------------------------
// bid: cell = bid>>5; sub = bid&31; jpair = sub>>1 (j0 = jpair*32); btile = sub&1.
// 8 warps K-split; A-frags persistent in 128 regs. All chunks prefetched at
// step start (4 commit groups, cascaded wait_group). Per-btile RMW-free flag
// barrier: each CTA stores its step to its own flag; warp0 polls all 64 flags
// of its btile with one u64 load per lane.
__global__ void __launch_bounds__(256, 1)
rec_kernel(float* __restrict__ dout) {
    extern __shared__ char smem[];
    const uint32_t smem_u = s2u(smem);
    const uint32_t vsm_u  = smem_u;
    float* redf = (float*)(smem + 4 * VBUF_BYTES);

    const int cell  = blockIdx.x >> 5;
    const int sub   = blockIdx.x & 31;
    const int jpair = sub >> 1;
    const int btile = sub & 1;
    const int j0    = jpair * JT;
    const int b0c   = btile * BT;
    const int tid   = threadIdx.x;
    const int w     = tid >> 5;
    const int lane  = tid & 31;
    const int g     = lane >> 2;
    const int tig   = lane & 3;

    const int Ktot   = (cell == 0) ? (INPS + HH) : (2 * HH);
    const int nchunk = Ktot / KC;          // 3 or 4

    // ---- load persistent A-fragments (hi+lo, 2 j-tiles) into registers ----
    uint32_t A[128];
    {
        const uint32_t a_off = ((uint32_t)(lane >> 3) << 7) + ((uint32_t)(lane & 7) << 4);
#pragma unroll
        for (int jt = 0; jt < 2; ++jt) {
            const int4* srcw = (const int4*)&g_WA[cell][jpair * 2 + jt][0][0][0];
            int4* dstw = (int4*)smem;
            const int n4 = (Ktot / 16) * 1024 / 16;
            for (int i = tid; i < n4; i += 256) dstw[i] = srcw[i];
            __syncthreads();
#pragma unroll
            for (int c = 0; c < 4; ++c) {
                if (c < nchunk) {
#pragma unroll
                    for (int i = 0; i < 2; ++i) {
                        const int kcg = c * 16 + w * 2 + i;
                        const uint32_t aw = smem_u + (uint32_t)kcg * 1024u + a_off;
                        const int ai = ((c * 2 + i) * 2 + jt) * 8;
                        ldsm_x4(A[ai + 0], A[ai + 1], A[ai + 2], A[ai + 3], aw);
                        ldsm_x4(A[ai + 4], A[ai + 5], A[ai + 6], A[ai + 7], aw + 512u);
                    }
                }
            }
            __syncthreads();
        }
    }

    const int jj  = tid >> 3;              // 0..31 epilogue j ownership
    const int b0e = (tid & 7) * 4;         // 0..28 epilogue b ownership
    const float bias_j = g_bias[cell][j0 + jj];

    const uint32_t b_lane = (uint32_t)(lane & 15) * (uint32_t)VROWB
                          + ((uint32_t)(lane >> 4) << 4);

    const int delay   = (cell == 0) ? 0 : ((cell == 2) ? 2 : 1);
    const int srccell = (cell == 2) ? 1 : 0;
    unsigned* myflag = &g_flag[btile][cell * 16 + jpair];
    const uint64_t* pollp = (const uint64_t*)&g_flag[btile][0];

    for (int s = 0; s < TT + 2; ++s) {
        const int t = s - delay;
        const bool active = (t >= 0) && (t < TT);
        if (active) {
            const int par = s & 1;

            // ---- issue ALL chunks up front (sources are ready post-barrier) ----
            for (int c = 0; c < nchunk; ++c) {
                issue_chunk(vsm_u + c * VBUF_BYTES, cell, c, t, par, srccell, b0c, tid);
                cp_commit();
            }

            float acc[2][4][4];
#pragma unroll
            for (int a = 0; a < 2; ++a)
#pragma unroll
                for (int q = 0; q < 4; ++q) {
                    acc[a][q][0] = 0.f; acc[a][q][1] = 0.f;
                    acc[a][q][2] = 0.f; acc[a][q][3] = 0.f;
                }

            for (int c = 0; c < nchunk; ++c) {
                cp_wait_n(nchunk - 1 - c);
                __syncthreads();
                const uint32_t vb = vsm_u + c * VBUF_BYTES + b_lane;
#pragma unroll
                for (int i = 0; i < 2; ++i) {
                    const uint32_t kb = vb + (uint32_t)((w * 2 + i) * 16) * (uint32_t)VROWB;
                    uint32_t bh[8], bl[8];
                    ldsm_x4t(bh[0], bh[1], bh[2], bh[3], kb);
                    ldsm_x4t(bh[4], bh[5], bh[6], bh[7], kb + 32u);
                    ldsm_x4t(bl[0], bl[1], bl[2], bl[3], kb + VPLANE_BYTES);
                    ldsm_x4t(bl[4], bl[5], bl[6], bl[7], kb + VPLANE_BYTES + 32u);
                    const int slot = c * 2 + i;
#pragma unroll
                    for (int jt = 0; jt < 2; ++jt) {
                        const uint32_t* Ah = &A[(slot * 2 + jt) * 8];
                        const uint32_t* Al = Ah + 4;
#pragma unroll
                        for (int q = 0; q < 4; ++q) {
                            const uint32_t q0 = bh[(q >> 1) * 4 + (q & 1) * 2];
                            const uint32_t q1 = bh[(q >> 1) * 4 + (q & 1) * 2 + 1];
                            const uint32_t l0 = bl[(q >> 1) * 4 + (q & 1) * 2];
                            const uint32_t l1 = bl[(q >> 1) * 4 + (q & 1) * 2 + 1];
                            mma_bf16(acc[jt][q], Ah[0], Ah[1], Ah[2], Ah[3], q0, q1);
                            mma_bf16(acc[jt][q], Ah[0], Ah[1], Ah[2], Ah[3], l0, l1);
                            mma_bf16(acc[jt][q], Al[0], Al[1], Al[2], Al[3], q0, q1);
                        }
                    }
                }
            }

            // ---- cross-warp K reduction ----
            {
                float* rw = redf + w * (JT * RS);
#pragma unroll
                for (int jt = 0; jt < 2; ++jt)
#pragma unroll
                    for (int q = 0; q < 4; ++q) {
                        const int b = q * 8 + tig * 2;
                        *(float2*)&rw[(jt * 16 + g) * RS + b] =
                            make_float2(acc[jt][q][0], acc[jt][q][1]);
                        *(float2*)&rw[(jt * 16 + g + 8) * RS + b] =
                            make_float2(acc[jt][q][2], acc[jt][q][3]);
                    }
            }
            __syncthreads();

            float4 sum = make_float4(bias_j, bias_j, bias_j, bias_j);
#pragma unroll
            for (int ww = 0; ww < 8; ++ww) {
                float4 v = *(const float4*)&redf[ww * (JT * RS) + jj * RS + b0e];
                sum.x += v.x; sum.y += v.y; sum.z += v.z; sum.w += v.w;
            }
            const float o0 = tanhf(sum.x), o1 = tanhf(sum.y);
            const float o2 = tanhf(sum.z), o3 = tanhf(sum.w);

            const int np = (s + 1) & 1;
            const int jg = j0 + jj;
            const int bg = b0c + b0e;
            uint32_t lo0, lo1;
            const uint32_t hi0 = pack_split(o0, o1, lo0);
            const uint32_t hi1 = pack_split(o2, o3, lo1);
            *(uint2*)&g_h2[cell][np][0][jg][bg] = make_uint2(hi0, hi1);
            *(uint2*)&g_h2[cell][np][1][jg][bg] = make_uint2(lo0, lo1);

            if (cell == 2 && t == TT - 1) {
                const uint16_t* shp = &g_h2[3][par][0][jg][bg];
                const uint16_t* slp = &g_h2[3][par][1][jg][bg];
#pragma unroll
                for (int q = 0; q < 4; ++q) {
                    float skip = __bfloat162float(__ushort_as_bfloat16(__ldcg(&shp[q])))
                               + __bfloat162float(__ushort_as_bfloat16(__ldcg(&slp[q])));
                    const float ov = (q == 0) ? o0 : (q == 1) ? o1 : (q == 2) ? o2 : o3;
                    dout[(bg + q) * HH + jg] = ov + skip;
                }
            }
        }

        // ---- per-btile flag barrier (RMW-free) ----
        __syncthreads();                     // all h writes done
        if (tid == 0) {
            asm volatile("st.release.gpu.u32 [%0], %1;"
                         :: "l"(myflag), "r"((unsigned)(s + 1)) : "memory");
        }
        if (tid < 32) {
            const unsigned need = (unsigned)(s + 1);
            const uint64_t* fp = pollp + lane;   // lane covers flags 2*lane, 2*lane+1
            uint64_t v;
            do {
                asm volatile("ld.relaxed.gpu.u64 %0, [%1];"
                             : "=l"(v) : "l"(fp) : "memory");
            } while (__any_sync(0xFFFFFFFFu,
                                ((unsigned)v < need) || ((unsigned)(v >> 32) < need)));
            asm volatile("fence.acq_rel.gpu;" ::: "memory");
        }
        __syncthreads();
    }
}

// ---------------- launch ------------------------------------------------------
extern "C" void kernel_launch(void* const* d_in, const int* in_sizes, int n_in,
                              void* d_out, int out_size) {
    (void)in_sizes; (void)n_in; (void)out_size;

    Params P;
    for (int i = 0; i < 20; ++i) P.p[i] = (const float*)d_in[i];

    cudaFuncSetAttribute(rec_kernel,
                         cudaFuncAttributeMaxDynamicSharedMemorySize, SMEM_TOTAL);

    init_kernel<<<128, 256>>>();
    prep_kernel<<<512, 256>>>(P);
    xconv_kernel<<<512, 256>>>((const float*)d_in[0]);
    rec_kernel<<<NCTA, 256, SMEM_TOTAL>>>((float*)d_out);
}

// round 12
// speedup vs baseline: 1.8070x; 1.8070x over previous
#include <cuda_runtime.h>
#include <cuda_bf16.h>
#include <math.h>
#include <stdint.h>

// Problem dims
#define TT   512
#define BB   64
#define INPS 256
#define HH   512

// Kernel config: per cell 16 j-pairs x 2 batch-halves = 32 CTAs; 4 cells = 128
#define NCTA 128
#define JT   32       // j rows per CTA (2 x 16-row tiles)
#define BT   32       // batch cols per CTA
#define KC   256      // K rows per chunk

// Smem layout
#define VROWB        80                     // staged k-row stride: 64B data + 16B pad
#define VPLANE_BYTES (KC * VROWB)           // 20480
#define VBUF_BYTES   (2 * VPLANE_BYTES)     // 40960 (hi+lo planes)
#define RS           36                     // reduction row stride (floats)
#define RED_BYTES    (8 * JT * RS * 4)      // 36864
#define SMEM_TOTAL   (4 * VBUF_BYTES + RED_BYTES)   // 200704

// ---------------- device scratch ---------------------------------------------
__device__ __align__(256) uint16_t g_WA[4][32][64][2][256];
__device__ __align__(256) float    g_bias[4][HH];
__device__ __align__(256) uint16_t g_x2[2][TT][INPS][BB];   // x bf16 hi/lo planes [p][t][i][b]
__device__ __align__(256) uint16_t g_h2[4][2][2][HH][BB];   // state [cell][parity][plane][j][b]
__device__ __align__(128) unsigned g_barx[2][32];           // per-btile barrier counters

struct Params { const float* p[20]; };

// ---------------- helpers -----------------------------------------------------
__device__ __forceinline__ uint32_t s2u(const void* p) {
    uint32_t a;
    asm("{ .reg .u64 t; cvta.to.shared.u64 t, %1; cvt.u32.u64 %0, t; }"
        : "=r"(a) : "l"(p));
    return a;
}

__device__ __forceinline__ void ldsm_x4(uint32_t& r0, uint32_t& r1,
                                        uint32_t& r2, uint32_t& r3, uint32_t addr) {
    asm volatile("ldmatrix.sync.aligned.m8n8.x4.shared.b16 {%0,%1,%2,%3}, [%4];"
                 : "=r"(r0), "=r"(r1), "=r"(r2), "=r"(r3) : "r"(addr));
}

__device__ __forceinline__ void ldsm_x4t(uint32_t& r0, uint32_t& r1,
                                         uint32_t& r2, uint32_t& r3, uint32_t addr) {
    asm volatile("ldmatrix.sync.aligned.m8n8.x4.trans.shared.b16 {%0,%1,%2,%3}, [%4];"
                 : "=r"(r0), "=r"(r1), "=r"(r2), "=r"(r3) : "r"(addr));
}

__device__ __forceinline__ void mma_bf16(float* c,
                                         uint32_t a0, uint32_t a1, uint32_t a2, uint32_t a3,
                                         uint32_t b0, uint32_t b1) {
    asm volatile("mma.sync.aligned.m16n8k16.row.col.f32.bf16.bf16.f32 "
                 "{%0,%1,%2,%3}, {%4,%5,%6,%7}, {%8,%9}, {%0,%1,%2,%3};"
                 : "+f"(c[0]), "+f"(c[1]), "+f"(c[2]), "+f"(c[3])
                 : "r"(a0), "r"(a1), "r"(a2), "r"(a3), "r"(b0), "r"(b1));
}

__device__ __forceinline__ void cp_async16(uint32_t dst, const void* src) {
    asm volatile("cp.async.cg.shared.global [%0], [%1], 16;" :: "r"(dst), "l"(src));
}
__device__ __forceinline__ void cp_commit() { asm volatile("cp.async.commit_group;"); }
__device__ __forceinline__ void cp_wait_n(int n) {
    switch (n) {
    case 0: asm volatile("cp.async.wait_group 0;" ::: "memory"); break;
    case 1: asm volatile("cp.async.wait_group 1;" ::: "memory"); break;
    case 2: asm volatile("cp.async.wait_group 2;" ::: "memory"); break;
    default: asm volatile("cp.async.wait_group 3;" ::: "memory"); break;
    }
}

__device__ __forceinline__ uint32_t pack_split(float x, float y, uint32_t& lopack) {
    __nv_bfloat16 hx = __float2bfloat16(x), hy = __float2bfloat16(y);
    __nv_bfloat16 lx = __float2bfloat16(x - __bfloat162float(hx));
    __nv_bfloat16 ly = __float2bfloat16(y - __bfloat162float(hy));
    lopack = (uint32_t)__bfloat16_as_ushort(lx) | ((uint32_t)__bfloat16_as_ushort(ly) << 16);
    return (uint32_t)__bfloat16_as_ushort(hx) | ((uint32_t)__bfloat16_as_ushort(hy) << 16);
}

// ---------------- init: zero states + barrier words ---------------------------
__global__ void init_kernel() {
    int idx = blockIdx.x * blockDim.x + threadIdx.x;
    int stride = gridDim.x * blockDim.x;
    uint32_t* h = (uint32_t*)&g_h2[0][0][0][0][0];
    const int n = (int)(sizeof(g_h2) / 4);
    for (int i = idx; i < n; i += stride) h[i] = 0u;
    if (idx < 64) ((unsigned*)g_barx)[idx] = 0u;
}

// ---------------- prep: split + tile weights, combine biases ------------------
__device__ __forceinline__ void put_w(int c, int j, int k, float w) {
    int jt = j >> 4, jl = j & 15, kc = k >> 4, kk = k & 15;
    int t = (jl >> 3) | ((kk >> 3) << 1);
    int off = t * 64 + (jl & 7) * 8 + (kk & 7);
    __nv_bfloat16 hi = __float2bfloat16(w);
    __nv_bfloat16 lo = __float2bfloat16(w - __bfloat162float(hi));
    g_WA[c][jt][kc][0][off] = __bfloat16_as_ushort(hi);
    g_WA[c][jt][kc][1][off] = __bfloat16_as_ushort(lo);
}

__global__ void prep_kernel(Params P) {
    int idx = blockIdx.x * blockDim.x + threadIdx.x;
    int stride = gridDim.x * blockDim.x;

    for (int i = idx; i < HH * INPS; i += stride) {
        int j = i / INPS, k = i - j * INPS;
        put_w(0, j, k, P.p[1][i]);
    }
    for (int i = idx; i < HH * HH; i += stride) {
        int j = i / HH, k = i - j * HH;
        put_w(0, j, INPS + k, P.p[3][i]);
    }
    const int ihI[3] = {5, 10, 15};
    const int mI[3]  = {6, 11, 16};
    const int hhI[3] = {8, 13, 18};
    for (int c = 0; c < 3; ++c) {
        const float* wih = P.p[ihI[c]];
        const float* msk = P.p[mI[c]];
        const float* whh = P.p[hhI[c]];
        for (int i = idx; i < HH * HH; i += stride) {
            int j = i / HH, k = i - j * HH;
            put_w(c + 1, j, k, wih[i] * msk[i]);
            put_w(c + 1, j, HH + k, whh[i]);
        }
    }
    const int bihI[4] = {2, 7, 12, 17};
    const int bhhI[4] = {4, 9, 14, 19};
    for (int i = idx; i < 4 * HH; i += stride) {
        int c = i / HH, j = i - c * HH;
        g_bias[c][j] = P.p[bihI[c]][j] + P.p[bhhI[c]][j];
    }
}

// ---------------- x convert: [t][b][i] fp32 -> hi/lo planes [p][t][i][b] -----
__global__ void xconv_kernel(const float* __restrict__ x) {
    int idx = blockIdx.x * blockDim.x + threadIdx.x;
    int stride = gridDim.x * blockDim.x;
    const int n = TT * INPS * BB;
    for (int e = idx; e < n; e += stride) {
        int t = e / (INPS * BB);
        int r = e - t * (INPS * BB);
        int i = r / BB, b = r - i * BB;
        float f = x[(t * BB + b) * INPS + i];
        __nv_bfloat16 hi = __float2bfloat16(f);
        __nv_bfloat16 lo = __float2bfloat16(f - __bfloat162float(hi));
        g_x2[0][t][i][b] = __bfloat16_as_ushort(hi);
        g_x2[1][t][i][b] = __bfloat16_as_ushort(lo);
    }
}

// ---------------- warp-private chunk staging ----------------------------------
// Warp w cp.asyncs ONLY k-rows [32w, 32w+32) of the chunk — exactly the rows
// its own ldsm/mma consume. cp.async.wait_group (per-thread) alone orders
// producer->consumer; no per-chunk CTA sync needed, and staging buffers are
// warp-private across steps as well.
__device__ __forceinline__ void issue_chunk_warp(uint32_t vdst, int cell, int c,
                                                 int t, int par, int srccell,
                                                 int b0c, int w, int lane) {
#pragma unroll
    for (int p = 0; p < 2; ++p) {
        const uint16_t* s;
        if (cell == 0)
            s = (c == 0) ? &g_x2[p][t][0][b0c]
                         : &g_h2[0][par][p][(c - 1) * KC][b0c];
        else
            s = (c < 2) ? &g_h2[srccell][par][p][c * KC][b0c]
                        : &g_h2[cell][par][p][(c - 2) * KC][b0c];
        const char* sb = (const char*)s;
        const uint32_t d = vdst + p * VPLANE_BYTES;
#pragma unroll
        for (int i = 0; i < 4; ++i) {
            const int e = i * 32 + lane;          // 0..127: row-in-slice = e>>2, seg = e&3
            const int r = 32 * w + (e >> 2);
            cp_async16(d + (uint32_t)r * (uint32_t)VROWB + (uint32_t)(e & 3) * 16u,
                       sb + (size_t)r * (BB * 2) + (size_t)(e & 3) * 16);
        }
    }
}

// ---------------- persistent pipelined recurrence -----------------------------
// bid: cell = bid>>5; sub = bid&31; jpair = sub>>1 (j0 = jpair*32); btile = sub&1.
// 8 warps K-split; A-frags persistent in 128 regs. All chunks prefetched at
// step start (4 commit groups, cascaded per-warp wait_group, no per-chunk CTA
// sync). Per-btile atomic-counter barrier (R7 protocol — best measured).
__global__ void __launch_bounds__(256, 1)
rec_kernel(float* __restrict__ dout) {
    extern __shared__ char smem[];
    const uint32_t smem_u = s2u(smem);
    const uint32_t vsm_u  = smem_u;
    float* redf = (float*)(smem + 4 * VBUF_BYTES);

    const int cell  = blockIdx.x >> 5;
    const int sub   = blockIdx.x & 31;
    const int jpair = sub >> 1;
    const int btile = sub & 1;
    const int j0    = jpair * JT;
    const int b0c   = btile * BT;
    const int tid   = threadIdx.x;
    const int w     = tid >> 5;
    const int lane  = tid & 31;
    const int g     = lane >> 2;
    const int tig   = lane & 3;

    const int Ktot   = (cell == 0) ? (INPS + HH) : (2 * HH);
    const int nchunk = Ktot / KC;          // 3 or 4

    // ---- load persistent A-fragments (hi+lo, 2 j-tiles) into registers ----
    uint32_t A[128];
    {
        const uint32_t a_off = ((uint32_t)(lane >> 3) << 7) + ((uint32_t)(lane & 7) << 4);
#pragma unroll
        for (int jt = 0; jt < 2; ++jt) {
            const int4* srcw = (const int4*)&g_WA[cell][jpair * 2 + jt][0][0][0];
            int4* dstw = (int4*)smem;
            const int n4 = (Ktot / 16) * 1024 / 16;
            for (int i = tid; i < n4; i += 256) dstw[i] = srcw[i];
            __syncthreads();
#pragma unroll
            for (int c = 0; c < 4; ++c) {
                if (c < nchunk) {
#pragma unroll
                    for (int i = 0; i < 2; ++i) {
                        const int kcg = c * 16 + w * 2 + i;
                        const uint32_t aw = smem_u + (uint32_t)kcg * 1024u + a_off;
                        const int ai = ((c * 2 + i) * 2 + jt) * 8;
                        ldsm_x4(A[ai + 0], A[ai + 1], A[ai + 2], A[ai + 3], aw);
                        ldsm_x4(A[ai + 4], A[ai + 5], A[ai + 6], A[ai + 7], aw + 512u);
                    }
                }
            }
            __syncthreads();
        }
    }

    const int jj  = tid >> 3;              // 0..31 epilogue j ownership
    const int b0e = (tid & 7) * 4;         // 0..28 epilogue b ownership
    const float bias_j = g_bias[cell][j0 + jj];

    const uint32_t b_lane = (uint32_t)(lane & 15) * (uint32_t)VROWB
                          + ((uint32_t)(lane >> 4) << 4);

    const int delay   = (cell == 0) ? 0 : ((cell == 2) ? 2 : 1);
    const int srccell = (cell == 2) ? 1 : 0;
    unsigned* barp = &g_barx[btile][0];
    unsigned bar_target = 0;

    for (int s = 0; s < TT + 2; ++s) {
        const int t = s - delay;
        const bool active = (t >= 0) && (t < TT);
        if (active) {
            const int par = s & 1;

            // ---- issue ALL chunks up front (sources are ready post-barrier) ----
            for (int c = 0; c < nchunk; ++c) {
                issue_chunk_warp(vsm_u + c * VBUF_BYTES, cell, c, t, par,
                                 srccell, b0c, w, lane);
                cp_commit();
            }

            float acc[2][4][4];
#pragma unroll
            for (int a = 0; a < 2; ++a)
#pragma unroll
                for (int q = 0; q < 4; ++q) {
                    acc[a][q][0] = 0.f; acc[a][q][1] = 0.f;
                    acc[a][q][2] = 0.f; acc[a][q][3] = 0.f;
                }

            // warp-local consume: cascade wait_group orders this warp's slices
            for (int c = 0; c < nchunk; ++c) {
                cp_wait_n(nchunk - 1 - c);
                const uint32_t vb = vsm_u + c * VBUF_BYTES + b_lane;
#pragma unroll
                for (int i = 0; i < 2; ++i) {
                    const uint32_t kb = vb + (uint32_t)((w * 2 + i) * 16) * (uint32_t)VROWB;
                    uint32_t bh[8], bl[8];
                    ldsm_x4t(bh[0], bh[1], bh[2], bh[3], kb);
                    ldsm_x4t(bh[4], bh[5], bh[6], bh[7], kb + 32u);
                    ldsm_x4t(bl[0], bl[1], bl[2], bl[3], kb + VPLANE_BYTES);
                    ldsm_x4t(bl[4], bl[5], bl[6], bl[7], kb + VPLANE_BYTES + 32u);
                    const int slot = c * 2 + i;
#pragma unroll
                    for (int jt = 0; jt < 2; ++jt) {
                        const uint32_t* Ah = &A[(slot * 2 + jt) * 8];
                        const uint32_t* Al = Ah + 4;
#pragma unroll
                        for (int q = 0; q < 4; ++q) {
                            const uint32_t q0 = bh[(q >> 1) * 4 + (q & 1) * 2];
                            const uint32_t q1 = bh[(q >> 1) * 4 + (q & 1) * 2 + 1];
                            const uint32_t l0 = bl[(q >> 1) * 4 + (q & 1) * 2];
                            const uint32_t l1 = bl[(q >> 1) * 4 + (q & 1) * 2 + 1];
                            mma_bf16(acc[jt][q], Ah[0], Ah[1], Ah[2], Ah[3], q0, q1);
                            mma_bf16(acc[jt][q], Ah[0], Ah[1], Ah[2], Ah[3], l0, l1);
                            mma_bf16(acc[jt][q], Al[0], Al[1], Al[2], Al[3], q0, q1);
                        }
                    }
                }
            }

            // ---- cross-warp K reduction ----
            {
                float* rw = redf + w * (JT * RS);
#pragma unroll
                for (int jt = 0; jt < 2; ++jt)
#pragma unroll
                    for (int q = 0; q < 4; ++q) {
                        const int b = q * 8 + tig * 2;
                        *(float2*)&rw[(jt * 16 + g) * RS + b] =
                            make_float2(acc[jt][q][0], acc[jt][q][1]);
                        *(float2*)&rw[(jt * 16 + g + 8) * RS + b] =
                            make_float2(acc[jt][q][2], acc[jt][q][3]);
                    }
            }
            __syncthreads();

            float4 sum = make_float4(bias_j, bias_j, bias_j, bias_j);
#pragma unroll
            for (int ww = 0; ww < 8; ++ww) {
                float4 v = *(const float4*)&redf[ww * (JT * RS) + jj * RS + b0e];
                sum.x += v.x; sum.y += v.y; sum.z += v.z; sum.w += v.w;
            }
            const float o0 = tanhf(sum.x), o1 = tanhf(sum.y);
            const float o2 = tanhf(sum.z), o3 = tanhf(sum.w);

            const int np = (s + 1) & 1;
            const int jg = j0 + jj;
            const int bg = b0c + b0e;
            uint32_t lo0, lo1;
            const uint32_t hi0 = pack_split(o0, o1, lo0);
            const uint32_t hi1 = pack_split(o2, o3, lo1);
            *(uint2*)&g_h2[cell][np][0][jg][bg] = make_uint2(hi0, hi1);
            *(uint2*)&g_h2[cell][np][1][jg][bg] = make_uint2(lo0, lo1);

            if (cell == 2 && t == TT - 1) {
                const uint16_t* shp = &g_h2[3][par][0][jg][bg];
                const uint16_t* slp = &g_h2[3][par][1][jg][bg];
#pragma unroll
                for (int q = 0; q < 4; ++q) {
                    float skip = __bfloat162float(__ushort_as_bfloat16(__ldcg(&shp[q])))
                               + __bfloat162float(__ushort_as_bfloat16(__ldcg(&slp[q])));
                    const float ov = (q == 0) ? o0 : (q == 1) ? o1 : (q == 2) ? o2 : o3;
                    dout[(bg + q) * HH + jg] = ov + skip;
                }
            }
        }

        // ---- per-btile barrier (R7 protocol: atomic counter + acquire spin) ----
        __syncthreads();
        if (tid == 0) {
            unsigned old;
            asm volatile("atom.add.release.gpu.u32 %0, [%1], 1;"
                         : "=r"(old) : "l"(barp) : "memory");
            bar_target += NCTA / 2;
            unsigned v;
            do {
                asm volatile("ld.acquire.gpu.u32 %0, [%1];"
                             : "=r"(v) : "l"(barp) : "memory");
            } while (v < bar_target);
        }
        __syncthreads();
    }
}

// ---------------- launch ------------------------------------------------------
extern "C" void kernel_launch(void* const* d_in, const int* in_sizes, int n_in,
                              void* d_out, int out_size) {
    (void)in_sizes; (void)n_in; (void)out_size;

    Params P;
    for (int i = 0; i < 20; ++i) P.p[i] = (const float*)d_in[i];

    cudaFuncSetAttribute(rec_kernel,
                         cudaFuncAttributeMaxDynamicSharedMemorySize, SMEM_TOTAL);

    init_kernel<<<128, 256>>>();
    prep_kernel<<<512, 256>>>(P);
    xconv_kernel<<<512, 256>>>((const float*)d_in[0]);
    rec_kernel<<<NCTA, 256, SMEM_TOTAL>>>((float*)d_out);
}

// round 13
// speedup vs baseline: 1.8255x; 1.0102x over previous
#include <cuda_runtime.h>
#include <cuda_bf16.h>
#include <math.h>
#include <stdint.h>

// Problem dims
#define TT   512
#define BB   64
#define INPS 256
#define HH   512

// Kernel config: per cell 16 j-pairs x 2 batch-halves = 32 CTAs; 4 cells = 128
#define NCTA 128
#define JT   32       // j rows per CTA (2 x 16-row tiles)
#define BT   32       // batch cols per CTA
#define KC   256      // K rows per chunk

// Smem layout
#define VROWB        80                     // staged k-row stride: 64B data + 16B pad
#define VPLANE_BYTES (KC * VROWB)           // 20480
#define VBUF_BYTES   (2 * VPLANE_BYTES)     // 40960 (hi+lo planes)
#define RS           36                     // reduction row stride (floats)
#define RED_BYTES    (8 * JT * RS * 4)      // 36864
#define SMEM_TOTAL   (4 * VBUF_BYTES + RED_BYTES)   // 200704

// ---------------- device scratch ---------------------------------------------
__device__ __align__(256) uint16_t g_WA[4][32][64][2][256];
__device__ __align__(256) float    g_bias[4][HH];
__device__ __align__(256) uint16_t g_x2[2][TT][INPS][BB];   // x bf16 hi/lo planes [p][t][i][b]
__device__ __align__(256) uint16_t g_h2[4][2][2][HH][BB];   // state [cell][parity][plane][j][b]
__device__ __align__(256) unsigned g_grp[8][32];            // per-(cell,btile) counters, 1/line

struct Params { const float* p[20]; };

// ---------------- helpers -----------------------------------------------------
__device__ __forceinline__ uint32_t s2u(const void* p) {
    uint32_t a;
    asm("{ .reg .u64 t; cvta.to.shared.u64 t, %1; cvt.u32.u64 %0, t; }"
        : "=r"(a) : "l"(p));
    return a;
}

__device__ __forceinline__ void ldsm_x4(uint32_t& r0, uint32_t& r1,
                                        uint32_t& r2, uint32_t& r3, uint32_t addr) {
    asm volatile("ldmatrix.sync.aligned.m8n8.x4.shared.b16 {%0,%1,%2,%3}, [%4];"
                 : "=r"(r0), "=r"(r1), "=r"(r2), "=r"(r3) : "r"(addr));
}

__device__ __forceinline__ void ldsm_x4t(uint32_t& r0, uint32_t& r1,
                                         uint32_t& r2, uint32_t& r3, uint32_t addr) {
    asm volatile("ldmatrix.sync.aligned.m8n8.x4.trans.shared.b16 {%0,%1,%2,%3}, [%4];"
                 : "=r"(r0), "=r"(r1), "=r"(r2), "=r"(r3) : "r"(addr));
}

__device__ __forceinline__ void mma_bf16(float* c,
                                         uint32_t a0, uint32_t a1, uint32_t a2, uint32_t a3,
                                         uint32_t b0, uint32_t b1) {
    asm volatile("mma.sync.aligned.m16n8k16.row.col.f32.bf16.bf16.f32 "
                 "{%0,%1,%2,%3}, {%4,%5,%6,%7}, {%8,%9}, {%0,%1,%2,%3};"
                 : "+f"(c[0]), "+f"(c[1]), "+f"(c[2]), "+f"(c[3])
                 : "r"(a0), "r"(a1), "r"(a2), "r"(a3), "r"(b0), "r"(b1));
}

__device__ __forceinline__ void cp_async16(uint32_t dst, const void* src) {
    asm volatile("cp.async.cg.shared.global [%0], [%1], 16;" :: "r"(dst), "l"(src));
}
__device__ __forceinline__ void cp_commit() { asm volatile("cp.async.commit_group;"); }
__device__ __forceinline__ void cp_wait_n(int n) {
    switch (n) {
    case 0: asm volatile("cp.async.wait_group 0;" ::: "memory"); break;
    case 1: asm volatile("cp.async.wait_group 1;" ::: "memory"); break;
    case 2: asm volatile("cp.async.wait_group 2;" ::: "memory"); break;
    default: asm volatile("cp.async.wait_group 3;" ::: "memory"); break;
    }
}

__device__ __forceinline__ uint32_t pack_split(float x, float y, uint32_t& lopack) {
    __nv_bfloat16 hx = __float2bfloat16(x), hy = __float2bfloat16(y);
    __nv_bfloat16 lx = __float2bfloat16(x - __bfloat162float(hx));
    __nv_bfloat16 ly = __float2bfloat16(y - __bfloat162float(hy));
    lopack = (uint32_t)__bfloat16_as_ushort(lx) | ((uint32_t)__bfloat16_as_ushort(ly) << 16);
    return (uint32_t)__bfloat16_as_ushort(hx) | ((uint32_t)__bfloat16_as_ushort(hy) << 16);
}

// ---------------- init: zero states + counters --------------------------------
__global__ void init_kernel() {
    int idx = blockIdx.x * blockDim.x + threadIdx.x;
    int stride = gridDim.x * blockDim.x;
    uint32_t* h = (uint32_t*)&g_h2[0][0][0][0][0];
    const int n = (int)(sizeof(g_h2) / 4);
    for (int i = idx; i < n; i += stride) h[i] = 0u;
    if (idx < 256) ((unsigned*)g_grp)[idx] = 0u;
}

// ---------------- prep: split + tile weights, combine biases ------------------
__device__ __forceinline__ void put_w(int c, int j, int k, float w) {
    int jt = j >> 4, jl = j & 15, kc = k >> 4, kk = k & 15;
    int t = (jl >> 3) | ((kk >> 3) << 1);
    int off = t * 64 + (jl & 7) * 8 + (kk & 7);
    __nv_bfloat16 hi = __float2bfloat16(w);
    __nv_bfloat16 lo = __float2bfloat16(w - __bfloat162float(hi));
    g_WA[c][jt][kc][0][off] = __bfloat16_as_ushort(hi);
    g_WA[c][jt][kc][1][off] = __bfloat16_as_ushort(lo);
}

__global__ void prep_kernel(Params P) {
    int idx = blockIdx.x * blockDim.x + threadIdx.x;
    int stride = gridDim.x * blockDim.x;

    for (int i = idx; i < HH * INPS; i += stride) {
        int j = i / INPS, k = i - j * INPS;
        put_w(0, j, k, P.p[1][i]);
    }
    for (int i = idx; i < HH * HH; i += stride) {
        int j = i / HH, k = i - j * HH;
        put_w(0, j, INPS + k, P.p[3][i]);
    }
    const int ihI[3] = {5, 10, 15};
    const int mI[3]  = {6, 11, 16};
    const int hhI[3] = {8, 13, 18};
    for (int c = 0; c < 3; ++c) {
        const float* wih = P.p[ihI[c]];
        const float* msk = P.p[mI[c]];
        const float* whh = P.p[hhI[c]];
        for (int i = idx; i < HH * HH; i += stride) {
            int j = i / HH, k = i - j * HH;
            put_w(c + 1, j, k, wih[i] * msk[i]);
            put_w(c + 1, j, HH + k, whh[i]);
        }
    }
    const int bihI[4] = {2, 7, 12, 17};
    const int bhhI[4] = {4, 9, 14, 19};
    for (int i = idx; i < 4 * HH; i += stride) {
        int c = i / HH, j = i - c * HH;
        g_bias[c][j] = P.p[bihI[c]][j] + P.p[bhhI[c]][j];
    }
}

// ---------------- x convert: [t][b][i] fp32 -> hi/lo planes [p][t][i][b] -----
__global__ void xconv_kernel(const float* __restrict__ x) {
    int idx = blockIdx.x * blockDim.x + threadIdx.x;
    int stride = gridDim.x * blockDim.x;
    const int n = TT * INPS * BB;
    for (int e = idx; e < n; e += stride) {
        int t = e / (INPS * BB);
        int r = e - t * (INPS * BB);
        int i = r / BB, b = r - i * BB;
        float f = x[(t * BB + b) * INPS + i];
        __nv_bfloat16 hi = __float2bfloat16(f);
        __nv_bfloat16 lo = __float2bfloat16(f - __bfloat162float(hi));
        g_x2[0][t][i][b] = __bfloat16_as_ushort(hi);
        g_x2[1][t][i][b] = __bfloat16_as_ushort(lo);
    }
}

// ---------------- warp-private chunk staging ----------------------------------
__device__ __forceinline__ void issue_chunk_warp(uint32_t vdst, int cell, int c,
                                                 int t, int par, int srccell,
                                                 int b0c, int w, int lane) {
#pragma unroll
    for (int p = 0; p < 2; ++p) {
        const uint16_t* s;
        if (cell == 0)
            s = (c == 0) ? &g_x2[p][t][0][b0c]
                         : &g_h2[0][par][p][(c - 1) * KC][b0c];
        else
            s = (c < 2) ? &g_h2[srccell][par][p][c * KC][b0c]
                        : &g_h2[cell][par][p][(c - 2) * KC][b0c];
        const char* sb = (const char*)s;
        const uint32_t d = vdst + p * VPLANE_BYTES;
#pragma unroll
        for (int i = 0; i < 4; ++i) {
            const int e = i * 32 + lane;          // 0..127: row-in-slice = e>>2, seg = e&3
            const int r = 32 * w + (e >> 2);
            cp_async16(d + (uint32_t)r * (uint32_t)VROWB + (uint32_t)(e & 3) * 16u,
                       sb + (size_t)r * (BB * 2) + (size_t)(e & 3) * 16);
        }
    }
}

// ---------------- persistent pipelined recurrence -----------------------------
// bid: cell = bid>>5; sub = bid&31; jpair = sub>>1 (j0 = jpair*32); btile = sub&1.
// 8 warps K-split; A-frags persistent in 128 regs; warp-private staging.
// Sync: 8 per-(cell,btile) counters. Each CTA arrives +1 per iteration; at
// iteration start it acquire-spins on its minimal dependency set >= 16*s.
__global__ void __launch_bounds__(256, 1)
rec_kernel(float* __restrict__ dout) {
    extern __shared__ char smem[];
    const uint32_t smem_u = s2u(smem);
    const uint32_t vsm_u  = smem_u;
    float* redf = (float*)(smem + 4 * VBUF_BYTES);

    const int cell  = blockIdx.x >> 5;
    const int sub   = blockIdx.x & 31;
    const int jpair = sub >> 1;
    const int btile = sub & 1;
    const int j0    = jpair * JT;
    const int b0c   = btile * BT;
    const int tid   = threadIdx.x;
    const int w     = tid >> 5;
    const int lane  = tid & 31;
    const int g     = lane >> 2;
    const int tig   = lane & 3;

    const int Ktot   = (cell == 0) ? (INPS + HH) : (2 * HH);
    const int nchunk = Ktot / KC;          // 3 or 4

    // ---- sync topology: arrive on own counter; wait on dependency set ----
    unsigned* cself = &g_grp[(cell << 1) | btile][0];
    unsigned* gof   = &g_grp[(0 << 1) | btile][0];
    unsigned* g1f   = &g_grp[(1 << 1) | btile][0];
    unsigned* g2f   = &g_grp[(2 << 1) | btile][0];
    unsigned* g3f   = &g_grp[(3 << 1) | btile][0];
    // wait pointers (3 per cell; duplicates harmless)
    unsigned* wp0 = cself;
    unsigned* wp1 = (cell == 0) ? g1f : (cell == 1) ? gof : (cell == 2) ? g1f : gof;
    unsigned* wp2 = (cell == 0) ? g3f : (cell == 1) ? g2f : (cell == 2) ? g3f : cself;
    unsigned* mywp = (tid == 0) ? wp0 : (tid == 1) ? wp1 : wp2;

    // ---- load persistent A-fragments (hi+lo, 2 j-tiles) into registers ----
    uint32_t A[128];
    {
        const uint32_t a_off = ((uint32_t)(lane >> 3) << 7) + ((uint32_t)(lane & 7) << 4);
#pragma unroll
        for (int jt = 0; jt < 2; ++jt) {
            const int4* srcw = (const int4*)&g_WA[cell][jpair * 2 + jt][0][0][0];
            int4* dstw = (int4*)smem;
            const int n4 = (Ktot / 16) * 1024 / 16;
            for (int i = tid; i < n4; i += 256) dstw[i] = srcw[i];
            __syncthreads();
#pragma unroll
            for (int c = 0; c < 4; ++c) {
                if (c < nchunk) {
#pragma unroll
                    for (int i = 0; i < 2; ++i) {
                        const int kcg = c * 16 + w * 2 + i;
                        const uint32_t aw = smem_u + (uint32_t)kcg * 1024u + a_off;
                        const int ai = ((c * 2 + i) * 2 + jt) * 8;
                        ldsm_x4(A[ai + 0], A[ai + 1], A[ai + 2], A[ai + 3], aw);
                        ldsm_x4(A[ai + 4], A[ai + 5], A[ai + 6], A[ai + 7], aw + 512u);
                    }
                }
            }
            __syncthreads();
        }
    }

    const int jj  = tid >> 3;              // 0..31 epilogue j ownership
    const int b0e = (tid & 7) * 4;         // 0..28 epilogue b ownership
    const float bias_j = g_bias[cell][j0 + jj];

    const uint32_t b_lane = (uint32_t)(lane & 15) * (uint32_t)VROWB
                          + ((uint32_t)(lane >> 4) << 4);

    const int delay   = (cell == 0) ? 0 : ((cell == 2) ? 2 : 1);
    const int srccell = (cell == 2) ? 1 : 0;

    for (int s = 0; s < TT + 2; ++s) {
        const int t = s - delay;
        const bool active = (t >= 0) && (t < TT);

        // cell0: static x chunk is dependency-free; issue before the wait
        if (cell == 0 && active) {
            issue_chunk_warp(vsm_u, 0, 0, t, s & 1, 0, b0c, w, lane);
            cp_commit();
        }

        // ---- step-start wait: dependency counters >= 16*s ----
        if (s > 0 && tid < 3) {
            const unsigned need = 16u * (unsigned)s;
            unsigned v;
            do {
                asm volatile("ld.acquire.gpu.u32 %0, [%1];"
                             : "=r"(v) : "l"(mywp) : "memory");
            } while (v < need);
        }
        __syncthreads();

        if (active) {
            const int par = s & 1;

            // ---- issue remaining chunks ----
            for (int c = (cell == 0) ? 1 : 0; c < nchunk; ++c) {
                issue_chunk_warp(vsm_u + c * VBUF_BYTES, cell, c, t, par,
                                 srccell, b0c, w, lane);
                cp_commit();
            }

            float acc[2][4][4];
#pragma unroll
            for (int a = 0; a < 2; ++a)
#pragma unroll
                for (int q = 0; q < 4; ++q) {
                    acc[a][q][0] = 0.f; acc[a][q][1] = 0.f;
                    acc[a][q][2] = 0.f; acc[a][q][3] = 0.f;
                }

            // warp-local consume: cascade wait_group orders this warp's slices
            for (int c = 0; c < nchunk; ++c) {
                cp_wait_n(nchunk - 1 - c);
                const uint32_t vb = vsm_u + c * VBUF_BYTES + b_lane;
#pragma unroll
                for (int i = 0; i < 2; ++i) {
                    const uint32_t kb = vb + (uint32_t)((w * 2 + i) * 16) * (uint32_t)VROWB;
                    uint32_t bh[8], bl[8];
                    ldsm_x4t(bh[0], bh[1], bh[2], bh[3], kb);
                    ldsm_x4t(bh[4], bh[5], bh[6], bh[7], kb + 32u);
                    ldsm_x4t(bl[0], bl[1], bl[2], bl[3], kb + VPLANE_BYTES);
                    ldsm_x4t(bl[4], bl[5], bl[6], bl[7], kb + VPLANE_BYTES + 32u);
                    const int slot = c * 2 + i;
#pragma unroll
                    for (int jt = 0; jt < 2; ++jt) {
                        const uint32_t* Ah = &A[(slot * 2 + jt) * 8];
                        const uint32_t* Al = Ah + 4;
#pragma unroll
                        for (int q = 0; q < 4; ++q) {
                            const uint32_t q0 = bh[(q >> 1) * 4 + (q & 1) * 2];
                            const uint32_t q1 = bh[(q >> 1) * 4 + (q & 1) * 2 + 1];
                            const uint32_t l0 = bl[(q >> 1) * 4 + (q & 1) * 2];
                            const uint32_t l1 = bl[(q >> 1) * 4 + (q & 1) * 2 + 1];
                            mma_bf16(acc[jt][q], Ah[0], Ah[1], Ah[2], Ah[3], q0, q1);
                            mma_bf16(acc[jt][q], Ah[0], Ah[1], Ah[2], Ah[3], l0, l1);
                            mma_bf16(acc[jt][q], Al[0], Al[1], Al[2], Al[3], q0, q1);
                        }
                    }
                }
            }

            // ---- cross-warp K reduction ----
            {
                float* rw = redf + w * (JT * RS);
#pragma unroll
                for (int jt = 0; jt < 2; ++jt)
#pragma unroll
                    for (int q = 0; q < 4; ++q) {
                        const int b = q * 8 + tig * 2;
                        *(float2*)&rw[(jt * 16 + g) * RS + b] =
                            make_float2(acc[jt][q][0], acc[jt][q][1]);
                        *(float2*)&rw[(jt * 16 + g + 8) * RS + b] =
                            make_float2(acc[jt][q][2], acc[jt][q][3]);
                    }
            }
            __syncthreads();

            float4 sum = make_float4(bias_j, bias_j, bias_j, bias_j);
#pragma unroll
            for (int ww = 0; ww < 8; ++ww) {
                float4 v = *(const float4*)&redf[ww * (JT * RS) + jj * RS + b0e];
                sum.x += v.x; sum.y += v.y; sum.z += v.z; sum.w += v.w;
            }
            const float o0 = tanhf(sum.x), o1 = tanhf(sum.y);
            const float o2 = tanhf(sum.z), o3 = tanhf(sum.w);

            const int np = (s + 1) & 1;
            const int jg = j0 + jj;
            const int bg = b0c + b0e;
            uint32_t lo0, lo1;
            const uint32_t hi0 = pack_split(o0, o1, lo0);
            const uint32_t hi1 = pack_split(o2, o3, lo1);
            *(uint2*)&g_h2[cell][np][0][jg][bg] = make_uint2(hi0, hi1);
            *(uint2*)&g_h2[cell][np][1][jg][bg] = make_uint2(lo0, lo1);

            if (cell == 2 && t == TT - 1) {
                const uint16_t* shp = &g_h2[3][par][0][jg][bg];
                const uint16_t* slp = &g_h2[3][par][1][jg][bg];
#pragma unroll
                for (int q = 0; q < 4; ++q) {
                    float skip = __bfloat162float(__ushort_as_bfloat16(__ldcg(&shp[q])))
                               + __bfloat162float(__ushort_as_bfloat16(__ldcg(&slp[q])));
                    const float ov = (q == 0) ? o0 : (q == 1) ? o1 : (q == 2) ? o2 : o3;
                    dout[(bg + q) * HH + jg] = ov + skip;
                }
            }
        }

        // ---- arrive: publish iteration completion on own group counter ----
        __syncthreads();                     // all h writes done
        if (tid == 0) {
            unsigned old;
            asm volatile("atom.add.release.gpu.u32 %0, [%1], 1;"
                         : "=r"(old) : "l"(cself) : "memory");
        }
    }
}

// ---------------- launch ------------------------------------------------------
extern "C" void kernel_launch(void* const* d_in, const int* in_sizes, int n_in,
                              void* d_out, int out_size) {
    (void)in_sizes; (void)n_in; (void)out_size;

    Params P;
    for (int i = 0; i < 20; ++i) P.p[i] = (const float*)d_in[i];

    cudaFuncSetAttribute(rec_kernel,
                         cudaFuncAttributeMaxDynamicSharedMemorySize, SMEM_TOTAL);

    init_kernel<<<128, 256>>>();
    prep_kernel<<<512, 256>>>(P);
    xconv_kernel<<<512, 256>>>((const float*)d_in[0]);
    rec_kernel<<<NCTA, 256, SMEM_TOTAL>>>((float*)d_out);
}

// round 14
// speedup vs baseline: 1.8382x; 1.0070x over previous
#include <cuda_runtime.h>
#include <cuda_bf16.h>
#include <math.h>
#include <stdint.h>

// Problem dims
#define TT   512
#define BB   64
#define INPS 256
#define HH   512

// Kernel config: per cell 16 j-pairs x 2 batch-halves = 32 CTAs; 4 cells = 128
#define NCTA 128
#define JT   32       // j rows per CTA (2 x 16-row tiles)
#define BT   32       // batch cols per CTA
#define KC   256      // K rows per chunk

// Smem layout
#define VROWB        80                     // staged k-row stride: 64B data + 16B pad
#define VPLANE_BYTES (KC * VROWB)           // 20480
#define VBUF_BYTES   (2 * VPLANE_BYTES)     // 40960 (hi+lo planes)
#define RS           36                     // reduction row stride (floats)
#define RED_BYTES    (8 * JT * RS * 4)      // 36864
#define SMEM_TOTAL   (4 * VBUF_BYTES + RED_BYTES)   // 200704

// ---------------- device scratch ---------------------------------------------
__device__ __align__(256) uint16_t g_WA[4][32][64][2][256];
__device__ __align__(256) float    g_bias[4][HH];
__device__ __align__(256) uint16_t g_x2[2][TT][INPS][BB];   // x bf16 hi/lo planes [p][t][i][b]
__device__ __align__(256) uint16_t g_h2[4][4][2][HH][BB];   // state ring: [cell][s&3][plane][j][b]
__device__ __align__(256) unsigned g_grp[8][32];            // per-(cell,btile) counters, 1/line

struct Params { const float* p[20]; };

// ---------------- helpers -----------------------------------------------------
__device__ __forceinline__ uint32_t s2u(const void* p) {
    uint32_t a;
    asm("{ .reg .u64 t; cvta.to.shared.u64 t, %1; cvt.u32.u64 %0, t; }"
        : "=r"(a) : "l"(p));
    return a;
}

__device__ __forceinline__ void ldsm_x4(uint32_t& r0, uint32_t& r1,
                                        uint32_t& r2, uint32_t& r3, uint32_t addr) {
    asm volatile("ldmatrix.sync.aligned.m8n8.x4.shared.b16 {%0,%1,%2,%3}, [%4];"
                 : "=r"(r0), "=r"(r1), "=r"(r2), "=r"(r3) : "r"(addr));
}

__device__ __forceinline__ void ldsm_x4t(uint32_t& r0, uint32_t& r1,
                                         uint32_t& r2, uint32_t& r3, uint32_t addr) {
    asm volatile("ldmatrix.sync.aligned.m8n8.x4.trans.shared.b16 {%0,%1,%2,%3}, [%4];"
                 : "=r"(r0), "=r"(r1), "=r"(r2), "=r"(r3) : "r"(addr));
}

__device__ __forceinline__ void mma_bf16(float* c,
                                         uint32_t a0, uint32_t a1, uint32_t a2, uint32_t a3,
                                         uint32_t b0, uint32_t b1) {
    asm volatile("mma.sync.aligned.m16n8k16.row.col.f32.bf16.bf16.f32 "
                 "{%0,%1,%2,%3}, {%4,%5,%6,%7}, {%8,%9}, {%0,%1,%2,%3};"
                 : "+f"(c[0]), "+f"(c[1]), "+f"(c[2]), "+f"(c[3])
                 : "r"(a0), "r"(a1), "r"(a2), "r"(a3), "r"(b0), "r"(b1));
}

__device__ __forceinline__ void cp_async16(uint32_t dst, const void* src) {
    asm volatile("cp.async.cg.shared.global [%0], [%1], 16;" :: "r"(dst), "l"(src));
}
__device__ __forceinline__ void cp_commit() { asm volatile("cp.async.commit_group;"); }
__device__ __forceinline__ void cp_wait_n(int n) {
    switch (n) {
    case 0: asm volatile("cp.async.wait_group 0;" ::: "memory"); break;
    case 1: asm volatile("cp.async.wait_group 1;" ::: "memory"); break;
    case 2: asm volatile("cp.async.wait_group 2;" ::: "memory"); break;
    default: asm volatile("cp.async.wait_group 3;" ::: "memory"); break;
    }
}

__device__ __forceinline__ uint32_t pack_split(float x, float y, uint32_t& lopack) {
    __nv_bfloat16 hx = __float2bfloat16(x), hy = __float2bfloat16(y);
    __nv_bfloat16 lx = __float2bfloat16(x - __bfloat162float(hx));
    __nv_bfloat16 ly = __float2bfloat16(y - __bfloat162float(hy));
    lopack = (uint32_t)__bfloat16_as_ushort(lx) | ((uint32_t)__bfloat16_as_ushort(ly) << 16);
    return (uint32_t)__bfloat16_as_ushort(hx) | ((uint32_t)__bfloat16_as_ushort(hy) << 16);
}

// ---------------- init: zero state ring + counters ----------------------------
__global__ void init_kernel() {
    int idx = blockIdx.x * blockDim.x + threadIdx.x;
    int stride = gridDim.x * blockDim.x;
    uint32_t* h = (uint32_t*)&g_h2[0][0][0][0][0];
    const int n = (int)(sizeof(g_h2) / 4);
    for (int i = idx; i < n; i += stride) h[i] = 0u;
    if (idx < 256) ((unsigned*)g_grp)[idx] = 0u;
}

// ---------------- prep: split + tile weights, combine biases ------------------
__device__ __forceinline__ void put_w(int c, int j, int k, float w) {
    int jt = j >> 4, jl = j & 15, kc = k >> 4, kk = k & 15;
    int t = (jl >> 3) | ((kk >> 3) << 1);
    int off = t * 64 + (jl & 7) * 8 + (kk & 7);
    __nv_bfloat16 hi = __float2bfloat16(w);
    __nv_bfloat16 lo = __float2bfloat16(w - __bfloat162float(hi));
    g_WA[c][jt][kc][0][off] = __bfloat16_as_ushort(hi);
    g_WA[c][jt][kc][1][off] = __bfloat16_as_ushort(lo);
}

__global__ void prep_kernel(Params P) {
    int idx = blockIdx.x * blockDim.x + threadIdx.x;
    int stride = gridDim.x * blockDim.x;

    for (int i = idx; i < HH * INPS; i += stride) {
        int j = i / INPS, k = i - j * INPS;
        put_w(0, j, k, P.p[1][i]);
    }
    for (int i = idx; i < HH * HH; i += stride) {
        int j = i / HH, k = i - j * HH;
        put_w(0, j, INPS + k, P.p[3][i]);
    }
    const int ihI[3] = {5, 10, 15};
    const int mI[3]  = {6, 11, 16};
    const int hhI[3] = {8, 13, 18};
    for (int c = 0; c < 3; ++c) {
        const float* wih = P.p[ihI[c]];
        const float* msk = P.p[mI[c]];
        const float* whh = P.p[hhI[c]];
        for (int i = idx; i < HH * HH; i += stride) {
            int j = i / HH, k = i - j * HH;
            put_w(c + 1, j, k, wih[i] * msk[i]);
            put_w(c + 1, j, HH + k, whh[i]);
        }
    }
    const int bihI[4] = {2, 7, 12, 17};
    const int bhhI[4] = {4, 9, 14, 19};
    for (int i = idx; i < 4 * HH; i += stride) {
        int c = i / HH, j = i - c * HH;
        g_bias[c][j] = P.p[bihI[c]][j] + P.p[bhhI[c]][j];
    }
}

// ---------------- x convert: [t][b][i] fp32 -> hi/lo planes [p][t][i][b] -----
__global__ void xconv_kernel(const float* __restrict__ x) {
    int idx = blockIdx.x * blockDim.x + threadIdx.x;
    int stride = gridDim.x * blockDim.x;
    const int n = TT * INPS * BB;
    for (int e = idx; e < n; e += stride) {
        int t = e / (INPS * BB);
        int r = e - t * (INPS * BB);
        int i = r / BB, b = r - i * BB;
        float f = x[(t * BB + b) * INPS + i];
        __nv_bfloat16 hi = __float2bfloat16(f);
        __nv_bfloat16 lo = __float2bfloat16(f - __bfloat162float(hi));
        g_x2[0][t][i][b] = __bfloat16_as_ushort(hi);
        g_x2[1][t][i][b] = __bfloat16_as_ushort(lo);
    }
}

// ---------------- warp-private chunk staging ----------------------------------
__device__ __forceinline__ void issue_chunk_warp(uint32_t vdst, int cell, int c,
                                                 int t, int par, int srccell,
                                                 int b0c, int w, int lane) {
#pragma unroll
    for (int p = 0; p < 2; ++p) {
        const uint16_t* s;
        if (cell == 0)
            s = (c == 0) ? &g_x2[p][t][0][b0c]
                         : &g_h2[0][par][p][(c - 1) * KC][b0c];
        else
            s = (c < 2) ? &g_h2[srccell][par][p][c * KC][b0c]
                        : &g_h2[cell][par][p][(c - 2) * KC][b0c];
        const char* sb = (const char*)s;
        const uint32_t d = vdst + p * VPLANE_BYTES;
#pragma unroll
        for (int i = 0; i < 4; ++i) {
            const int e = i * 32 + lane;          // 0..127: row-in-slice = e>>2, seg = e&3
            const int r = 32 * w + (e >> 2);
            cp_async16(d + (uint32_t)r * (uint32_t)VROWB + (uint32_t)(e & 3) * 16u,
                       sb + (size_t)r * (BB * 2) + (size_t)(e & 3) * 16);
        }
    }
}

// ---------------- persistent pipelined recurrence -----------------------------
// bid: cell = bid>>5; sub = bid&31; jpair = sub>>1 (j0 = jpair*32); btile = sub&1.
// 8 warps K-split; A-frags persistent in 128 regs; warp-private staging.
// State in a 4-deep parity ring: write (s+1)&3, read s&3. Waits:
//   data (off=0): self; producer — counter >= 16*s
//   backpressure (off=2): consumers — counter >= 16*(s-2)  (2 steps of slack)
__global__ void __launch_bounds__(256, 1)
rec_kernel(float* __restrict__ dout) {
    extern __shared__ char smem[];
    const uint32_t smem_u = s2u(smem);
    const uint32_t vsm_u  = smem_u;
    float* redf = (float*)(smem + 4 * VBUF_BYTES);

    const int cell  = blockIdx.x >> 5;
    const int sub   = blockIdx.x & 31;
    const int jpair = sub >> 1;
    const int btile = sub & 1;
    const int j0    = jpair * JT;
    const int b0c   = btile * BT;
    const int tid   = threadIdx.x;
    const int w     = tid >> 5;
    const int lane  = tid & 31;
    const int g     = lane >> 2;
    const int tig   = lane & 3;

    const int Ktot   = (cell == 0) ? (INPS + HH) : (2 * HH);
    const int nchunk = Ktot / KC;          // 3 or 4

    // ---- sync topology ----
    unsigned* cself = &g_grp[(cell << 1) | btile][0];
    unsigned* gof   = &g_grp[(0 << 1) | btile][0];
    unsigned* g1f   = &g_grp[(1 << 1) | btile][0];
    unsigned* g2f   = &g_grp[(2 << 1) | btile][0];
    unsigned* g3f   = &g_grp[(3 << 1) | btile][0];
    // waiter assignment per thread 0..2: (pointer, slack-offset)
    unsigned* mywp =
        (cell == 0) ? ((tid == 0) ? cself : (tid == 1) ? g1f : g3f)
      : (cell == 1) ? ((tid == 0) ? cself : (tid == 1) ? gof : g2f)
      : (cell == 2) ? ((tid == 0) ? cself : (tid == 1) ? g1f : g3f)
                    : ((tid == 0) ? cself : gof);
    const int myoff =
        (cell == 0) ? ((tid == 0) ? 0 : 2)
      : (cell == 1) ? ((tid == 2) ? 2 : 0)
      : (cell == 2) ? ((tid == 2) ? 2 : 0)   // g3f relaxed; full-strength at final step
                    : 0;

    // ---- load persistent A-fragments (hi+lo, 2 j-tiles) into registers ----
    uint32_t A[128];
    {
        const uint32_t a_off = ((uint32_t)(lane >> 3) << 7) + ((uint32_t)(lane & 7) << 4);
#pragma unroll
        for (int jt = 0; jt < 2; ++jt) {
            const int4* srcw = (const int4*)&g_WA[cell][jpair * 2 + jt][0][0][0];
            int4* dstw = (int4*)smem;
            const int n4 = (Ktot / 16) * 1024 / 16;
            for (int i = tid; i < n4; i += 256) dstw[i] = srcw[i];
            __syncthreads();
#pragma unroll
            for (int c = 0; c < 4; ++c) {
                if (c < nchunk) {
#pragma unroll
                    for (int i = 0; i < 2; ++i) {
                        const int kcg = c * 16 + w * 2 + i;
                        const uint32_t aw = smem_u + (uint32_t)kcg * 1024u + a_off;
                        const int ai = ((c * 2 + i) * 2 + jt) * 8;
                        ldsm_x4(A[ai + 0], A[ai + 1], A[ai + 2], A[ai + 3], aw);
                        ldsm_x4(A[ai + 4], A[ai + 5], A[ai + 6], A[ai + 7], aw + 512u);
                    }
                }
            }
            __syncthreads();
        }
    }

    const int jj  = tid >> 3;              // 0..31 epilogue j ownership
    const int b0e = (tid & 7) * 4;         // 0..28 epilogue b ownership
    const float bias_j = g_bias[cell][j0 + jj];

    const uint32_t b_lane = (uint32_t)(lane & 15) * (uint32_t)VROWB
                          + ((uint32_t)(lane >> 4) << 4);

    const int delay   = (cell == 0) ? 0 : ((cell == 2) ? 2 : 1);
    const int srccell = (cell == 2) ? 1 : 0;

    for (int s = 0; s < TT + 2; ++s) {
        const int t = s - delay;
        const bool active = (t >= 0) && (t < TT);

        // cell0: static x chunk is dependency-free; issue before the wait
        if (cell == 0 && active) {
            issue_chunk_warp(vsm_u, 0, 0, t, s & 3, 0, b0c, w, lane);
            cp_commit();
        }

        // ---- step-start waits ----
        if (tid < 3) {
            int off = myoff;
            if (cell == 2 && tid == 2 && s == TT + 1) off = 0;  // final skip read
            if (s > off) {
                const unsigned need = 16u * (unsigned)(s - off);
                unsigned v;
                do {
                    asm volatile("ld.acquire.gpu.u32 %0, [%1];"
                                 : "=r"(v) : "l"(mywp) : "memory");
                } while (v < need);
            }
        }
        __syncthreads();

        if (active) {
            const int par = s & 3;

            // ---- issue remaining chunks ----
            for (int c = (cell == 0) ? 1 : 0; c < nchunk; ++c) {
                issue_chunk_warp(vsm_u + c * VBUF_BYTES, cell, c, t, par,
                                 srccell, b0c, w, lane);
                cp_commit();
            }

            float acc[2][4][4];
#pragma unroll
            for (int a = 0; a < 2; ++a)
#pragma unroll
                for (int q = 0; q < 4; ++q) {
                    acc[a][q][0] = 0.f; acc[a][q][1] = 0.f;
                    acc[a][q][2] = 0.f; acc[a][q][3] = 0.f;
                }

            // warp-local consume: cascade wait_group orders this warp's slices
            for (int c = 0; c < nchunk; ++c) {
                cp_wait_n(nchunk - 1 - c);
                const uint32_t vb = vsm_u + c * VBUF_BYTES + b_lane;
#pragma unroll
                for (int i = 0; i < 2; ++i) {
                    const uint32_t kb = vb + (uint32_t)((w * 2 + i) * 16) * (uint32_t)VROWB;
                    uint32_t bh[8], bl[8];
                    ldsm_x4t(bh[0], bh[1], bh[2], bh[3], kb);
                    ldsm_x4t(bh[4], bh[5], bh[6], bh[7], kb + 32u);
                    ldsm_x4t(bl[0], bl[1], bl[2], bl[3], kb + VPLANE_BYTES);
                    ldsm_x4t(bl[4], bl[5], bl[6], bl[7], kb + VPLANE_BYTES + 32u);
                    const int slot = c * 2 + i;
#pragma unroll
                    for (int jt = 0; jt < 2; ++jt) {
                        const uint32_t* Ah = &A[(slot * 2 + jt) * 8];
                        const uint32_t* Al = Ah + 4;
#pragma unroll
                        for (int q = 0; q < 4; ++q) {
                            const uint32_t q0 = bh[(q >> 1) * 4 + (q & 1) * 2];
                            const uint32_t q1 = bh[(q >> 1) * 4 + (q & 1) * 2 + 1];
                            const uint32_t l0 = bl[(q >> 1) * 4 + (q & 1) * 2];
                            const uint32_t l1 = bl[(q >> 1) * 4 + (q & 1) * 2 + 1];
                            mma_bf16(acc[jt][q], Ah[0], Ah[1], Ah[2], Ah[3], q0, q1);
                            mma_bf16(acc[jt][q], Ah[0], Ah[1], Ah[2], Ah[3], l0, l1);
                            mma_bf16(acc[jt][q], Al[0], Al[1], Al[2], Al[3], q0, q1);
                        }
                    }
                }
            }

            // ---- cross-warp K reduction ----
            {
                float* rw = redf + w * (JT * RS);
#pragma unroll
                for (int jt = 0; jt < 2; ++jt)
#pragma unroll
                    for (int q = 0; q < 4; ++q) {
                        const int b = q * 8 + tig * 2;
                        *(float2*)&rw[(jt * 16 + g) * RS + b] =
                            make_float2(acc[jt][q][0], acc[jt][q][1]);
                        *(float2*)&rw[(jt * 16 + g + 8) * RS + b] =
                            make_float2(acc[jt][q][2], acc[jt][q][3]);
                    }
            }
            __syncthreads();

            float4 sum = make_float4(bias_j, bias_j, bias_j, bias_j);
#pragma unroll
            for (int ww = 0; ww < 8; ++ww) {
                float4 v = *(const float4*)&redf[ww * (JT * RS) + jj * RS + b0e];
                sum.x += v.x; sum.y += v.y; sum.z += v.z; sum.w += v.w;
            }
            const float o0 = tanhf(sum.x), o1 = tanhf(sum.y);
            const float o2 = tanhf(sum.z), o3 = tanhf(sum.w);

            const int np = (s + 1) & 3;
            const int jg = j0 + jj;
            const int bg = b0c + b0e;
            uint32_t lo0, lo1;
            const uint32_t hi0 = pack_split(o0, o1, lo0);
            const uint32_t hi1 = pack_split(o2, o3, lo1);
            *(uint2*)&g_h2[cell][np][0][jg][bg] = make_uint2(hi0, hi1);
            *(uint2*)&g_h2[cell][np][1][jg][bg] = make_uint2(lo0, lo1);

            if (cell == 2 && t == TT - 1) {
                const uint16_t* shp = &g_h2[3][par][0][jg][bg];
                const uint16_t* slp = &g_h2[3][par][1][jg][bg];
#pragma unroll
                for (int q = 0; q < 4; ++q) {
                    float skip = __bfloat162float(__ushort_as_bfloat16(__ldcg(&shp[q])))
                               + __bfloat162float(__ushort_as_bfloat16(__ldcg(&slp[q])));
                    const float ov = (q == 0) ? o0 : (q == 1) ? o1 : (q == 2) ? o2 : o3;
                    dout[(bg + q) * HH + jg] = ov + skip;
                }
            }
        }

        // ---- arrive: publish iteration completion on own group counter ----
        __syncthreads();                     // all h writes done
        if (tid == 0) {
            unsigned old;
            asm volatile("atom.add.release.gpu.u32 %0, [%1], 1;"
                         : "=r"(old) : "l"(cself) : "memory");
        }
    }
}

// ---------------- launch ------------------------------------------------------
extern "C" void kernel_launch(void* const* d_in, const int* in_sizes, int n_in,
                              void* d_out, int out_size) {
    (void)in_sizes; (void)n_in; (void)out_size;

    Params P;
    for (int i = 0; i < 20; ++i) P.p[i] = (const float*)d_in[i];

    cudaFuncSetAttribute(rec_kernel,
                         cudaFuncAttributeMaxDynamicSharedMemorySize, SMEM_TOTAL);

    init_kernel<<<128, 256>>>();
    prep_kernel<<<512, 256>>>(P);
    xconv_kernel<<<512, 256>>>((const float*)d_in[0]);
    rec_kernel<<<NCTA, 256, SMEM_TOTAL>>>((float*)d_out);
}

// round 15
// speedup vs baseline: 2.6625x; 1.4484x over previous
#include <cuda_runtime.h>
#include <cuda_fp16.h>
#include <math.h>
#include <stdint.h>

// Problem dims
#define TT   512
#define BB   64
#define INPS 256
#define HH   512

// Kernel config: per cell 16 j-pairs x 2 batch-halves = 32 CTAs; 4 cells = 128
#define NCTA 128
#define JT   32       // j rows per CTA (2 x 16-row tiles)
#define BT   32       // batch cols per CTA
#define KC   256      // K rows per chunk

// Smem layout (single fp16 activation plane)
#define VROWB        80                     // staged k-row stride: 64B data + 16B pad
#define VBUF_BYTES   (KC * VROWB)           // 20480 per chunk
#define RS           36                     // reduction row stride (floats)
#define RED_BYTES    (8 * JT * RS * 4)      // 36864
#define SMEM_TOTAL   (4 * VBUF_BYTES + RED_BYTES)   // 118784

// ---------------- device scratch ---------------------------------------------
// Weights: fp16 hi/lo 2-term split, ldmatrix-tiled: [cell][jtile16][kc][hl][256]
__device__ __align__(256) uint16_t g_WA[4][32][64][2][256];
__device__ __align__(256) float    g_bias[4][HH];
__device__ __align__(256) uint16_t g_x2[TT][INPS][BB];      // x fp16, [t][i][b]
__device__ __align__(256) uint16_t g_h2[4][4][HH][BB];      // state ring fp16: [cell][s&3][j][b]
__device__ __align__(256) unsigned g_grp[8][32];            // per-(cell,btile) counters

struct Params { const float* p[20]; };

// ---------------- helpers -----------------------------------------------------
__device__ __forceinline__ uint32_t s2u(const void* p) {
    uint32_t a;
    asm("{ .reg .u64 t; cvta.to.shared.u64 t, %1; cvt.u32.u64 %0, t; }"
        : "=r"(a) : "l"(p));
    return a;
}

__device__ __forceinline__ void ldsm_x4(uint32_t& r0, uint32_t& r1,
                                        uint32_t& r2, uint32_t& r3, uint32_t addr) {
    asm volatile("ldmatrix.sync.aligned.m8n8.x4.shared.b16 {%0,%1,%2,%3}, [%4];"
                 : "=r"(r0), "=r"(r1), "=r"(r2), "=r"(r3) : "r"(addr));
}

__device__ __forceinline__ void ldsm_x4t(uint32_t& r0, uint32_t& r1,
                                         uint32_t& r2, uint32_t& r3, uint32_t addr) {
    asm volatile("ldmatrix.sync.aligned.m8n8.x4.trans.shared.b16 {%0,%1,%2,%3}, [%4];"
                 : "=r"(r0), "=r"(r1), "=r"(r2), "=r"(r3) : "r"(addr));
}

__device__ __forceinline__ void mma_f16(float* c,
                                        uint32_t a0, uint32_t a1, uint32_t a2, uint32_t a3,
                                        uint32_t b0, uint32_t b1) {
    asm volatile("mma.sync.aligned.m16n8k16.row.col.f32.f16.f16.f32 "
                 "{%0,%1,%2,%3}, {%4,%5,%6,%7}, {%8,%9}, {%0,%1,%2,%3};"
                 : "+f"(c[0]), "+f"(c[1]), "+f"(c[2]), "+f"(c[3])
                 : "r"(a0), "r"(a1), "r"(a2), "r"(a3), "r"(b0), "r"(b1));
}

__device__ __forceinline__ void cp_async16(uint32_t dst, const void* src) {
    asm volatile("cp.async.cg.shared.global [%0], [%1], 16;" :: "r"(dst), "l"(src));
}
__device__ __forceinline__ void cp_commit() { asm volatile("cp.async.commit_group;"); }
__device__ __forceinline__ void cp_wait_n(int n) {
    switch (n) {
    case 0: asm volatile("cp.async.wait_group 0;" ::: "memory"); break;
    case 1: asm volatile("cp.async.wait_group 1;" ::: "memory"); break;
    case 2: asm volatile("cp.async.wait_group 2;" ::: "memory"); break;
    default: asm volatile("cp.async.wait_group 3;" ::: "memory"); break;
    }
}

// ---------------- init: zero state ring + counters ----------------------------
__global__ void init_kernel() {
    int idx = blockIdx.x * blockDim.x + threadIdx.x;
    int stride = gridDim.x * blockDim.x;
    uint32_t* h = (uint32_t*)&g_h2[0][0][0][0];
    const int n = (int)(sizeof(g_h2) / 4);
    for (int i = idx; i < n; i += stride) h[i] = 0u;
    if (idx < 256) ((unsigned*)g_grp)[idx] = 0u;
}

// ---------------- prep: fp16-split + tile weights, combine biases -------------
__device__ __forceinline__ void put_w(int c, int j, int k, float w) {
    int jt = j >> 4, jl = j & 15, kc = k >> 4, kk = k & 15;
    int t = (jl >> 3) | ((kk >> 3) << 1);
    int off = t * 64 + (jl & 7) * 8 + (kk & 7);
    __half hi = __float2half(w);
    __half lo = __float2half(w - __half2float(hi));
    g_WA[c][jt][kc][0][off] = __half_as_ushort(hi);
    g_WA[c][jt][kc][1][off] = __half_as_ushort(lo);
}

__global__ void prep_kernel(Params P) {
    int idx = blockIdx.x * blockDim.x + threadIdx.x;
    int stride = gridDim.x * blockDim.x;

    for (int i = idx; i < HH * INPS; i += stride) {
        int j = i / INPS, k = i - j * INPS;
        put_w(0, j, k, P.p[1][i]);
    }
    for (int i = idx; i < HH * HH; i += stride) {
        int j = i / HH, k = i - j * HH;
        put_w(0, j, INPS + k, P.p[3][i]);
    }
    const int ihI[3] = {5, 10, 15};
    const int mI[3]  = {6, 11, 16};
    const int hhI[3] = {8, 13, 18};
    for (int c = 0; c < 3; ++c) {
        const float* wih = P.p[ihI[c]];
        const float* msk = P.p[mI[c]];
        const float* whh = P.p[hhI[c]];
        for (int i = idx; i < HH * HH; i += stride) {
            int j = i / HH, k = i - j * HH;
            put_w(c + 1, j, k, wih[i] * msk[i]);
            put_w(c + 1, j, HH + k, whh[i]);
        }
    }
    const int bihI[4] = {2, 7, 12, 17};
    const int bhhI[4] = {4, 9, 14, 19};
    for (int i = idx; i < 4 * HH; i += stride) {
        int c = i / HH, j = i - c * HH;
        g_bias[c][j] = P.p[bihI[c]][j] + P.p[bhhI[c]][j];
    }
}

// ---------------- x convert: [t][b][i] fp32 -> fp16 [t][i][b] -----------------
__global__ void xconv_kernel(const float* __restrict__ x) {
    int idx = blockIdx.x * blockDim.x + threadIdx.x;
    int stride = gridDim.x * blockDim.x;
    const int n = TT * INPS * BB;
    for (int e = idx; e < n; e += stride) {
        int t = e / (INPS * BB);
        int r = e - t * (INPS * BB);
        int i = r / BB, b = r - i * BB;
        g_x2[t][i][b] = __half_as_ushort(__float2half(x[(t * BB + b) * INPS + i]));
    }
}

// ---------------- warp-private chunk staging (single fp16 plane) --------------
__device__ __forceinline__ void issue_chunk_warp(uint32_t vdst, int cell, int c,
                                                 int t, int par, int srccell,
                                                 int b0c, int w, int lane) {
    const uint16_t* s;
    if (cell == 0)
        s = (c == 0) ? &g_x2[t][0][b0c]
                     : &g_h2[0][par][(c - 1) * KC][b0c];
    else
        s = (c < 2) ? &g_h2[srccell][par][c * KC][b0c]
                    : &g_h2[cell][par][(c - 2) * KC][b0c];
    const char* sb = (const char*)s;
#pragma unroll
    for (int i = 0; i < 4; ++i) {
        const int e = i * 32 + lane;          // 0..127: row-in-slice = e>>2, seg = e&3
        const int r = 32 * w + (e >> 2);
        cp_async16(vdst + (uint32_t)r * (uint32_t)VROWB + (uint32_t)(e & 3) * 16u,
                   sb + (size_t)r * (BB * 2) + (size_t)(e & 3) * 16);
    }
}

// ---------------- persistent pipelined recurrence -----------------------------
// bid: cell = bid>>5; sub = bid&31; jpair = sub>>1 (j0 = jpair*32); btile = sub&1.
// 8 warps K-split; fp16 A-frags (hi+lo) persistent in 128 regs; single fp16
// activation plane; 2 MMA terms per k16 (whi*v + wlo*v). 4-deep state ring,
// per-(cell,btile) counters with relaxed backpressure (R13 protocol).
__global__ void __launch_bounds__(256, 1)
rec_kernel(float* __restrict__ dout) {
    extern __shared__ char smem[];
    const uint32_t smem_u = s2u(smem);
    const uint32_t vsm_u  = smem_u;
    float* redf = (float*)(smem + 4 * VBUF_BYTES);

    const int cell  = blockIdx.x >> 5;
    const int sub   = blockIdx.x & 31;
    const int jpair = sub >> 1;
    const int btile = sub & 1;
    const int j0    = jpair * JT;
    const int b0c   = btile * BT;
    const int tid   = threadIdx.x;
    const int w     = tid >> 5;
    const int lane  = tid & 31;
    const int g     = lane >> 2;
    const int tig   = lane & 3;

    const int Ktot   = (cell == 0) ? (INPS + HH) : (2 * HH);
    const int nchunk = Ktot / KC;          // 3 or 4

    // ---- sync topology (R13) ----
    unsigned* cself = &g_grp[(cell << 1) | btile][0];
    unsigned* gof   = &g_grp[(0 << 1) | btile][0];
    unsigned* g1f   = &g_grp[(1 << 1) | btile][0];
    unsigned* g2f   = &g_grp[(2 << 1) | btile][0];
    unsigned* g3f   = &g_grp[(3 << 1) | btile][0];
    unsigned* mywp =
        (cell == 0) ? ((tid == 0) ? cself : (tid == 1) ? g1f : g3f)
      : (cell == 1) ? ((tid == 0) ? cself : (tid == 1) ? gof : g2f)
      : (cell == 2) ? ((tid == 0) ? cself : (tid == 1) ? g1f : g3f)
                    : ((tid == 0) ? cself : gof);
    const int myoff =
        (cell == 0) ? ((tid == 0) ? 0 : 2)
      : (cell == 1) ? ((tid == 2) ? 2 : 0)
      : (cell == 2) ? ((tid == 2) ? 2 : 0)
                    : 0;

    // ---- load persistent A-fragments (hi+lo, 2 j-tiles) into registers ----
    uint32_t A[128];
    {
        const uint32_t a_off = ((uint32_t)(lane >> 3) << 7) + ((uint32_t)(lane & 7) << 4);
#pragma unroll
        for (int jt = 0; jt < 2; ++jt) {
            const int4* srcw = (const int4*)&g_WA[cell][jpair * 2 + jt][0][0][0];
            int4* dstw = (int4*)smem;
            const int n4 = (Ktot / 16) * 1024 / 16;
            for (int i = tid; i < n4; i += 256) dstw[i] = srcw[i];
            __syncthreads();
#pragma unroll
            for (int c = 0; c < 4; ++c) {
                if (c < nchunk) {
#pragma unroll
                    for (int i = 0; i < 2; ++i) {
                        const int kcg = c * 16 + w * 2 + i;
                        const uint32_t aw = smem_u + (uint32_t)kcg * 1024u + a_off;
                        const int ai = ((c * 2 + i) * 2 + jt) * 8;
                        ldsm_x4(A[ai + 0], A[ai + 1], A[ai + 2], A[ai + 3], aw);
                        ldsm_x4(A[ai + 4], A[ai + 5], A[ai + 6], A[ai + 7], aw + 512u);
                    }
                }
            }
            __syncthreads();
        }
    }

    const int jj  = tid >> 3;              // 0..31 epilogue j ownership
    const int b0e = (tid & 7) * 4;         // 0..28 epilogue b ownership
    const float bias_j = g_bias[cell][j0 + jj];

    const uint32_t b_lane = (uint32_t)(lane & 15) * (uint32_t)VROWB
                          + ((uint32_t)(lane >> 4) << 4);

    const int delay   = (cell == 0) ? 0 : ((cell == 2) ? 2 : 1);
    const int srccell = (cell == 2) ? 1 : 0;

    for (int s = 0; s < TT + 2; ++s) {
        const int t = s - delay;
        const bool active = (t >= 0) && (t < TT);

        // cell0: static x chunk is dependency-free; issue before the wait
        if (cell == 0 && active) {
            issue_chunk_warp(vsm_u, 0, 0, t, s & 3, 0, b0c, w, lane);
            cp_commit();
        }

        // ---- step-start waits ----
        if (tid < 3) {
            int off = myoff;
            if (cell == 2 && tid == 2 && s == TT + 1) off = 0;  // final skip read
            if (s > off) {
                const unsigned need = 16u * (unsigned)(s - off);
                unsigned v;
                do {
                    asm volatile("ld.acquire.gpu.u32 %0, [%1];"
                                 : "=r"(v) : "l"(mywp) : "memory");
                } while (v < need);
            }
        }
        __syncthreads();

        if (active) {
            const int par = s & 3;

            // ---- issue remaining chunks ----
            for (int c = (cell == 0) ? 1 : 0; c < nchunk; ++c) {
                issue_chunk_warp(vsm_u + c * VBUF_BYTES, cell, c, t, par,
                                 srccell, b0c, w, lane);
                cp_commit();
            }

            float acc[2][4][4];
#pragma unroll
            for (int a = 0; a < 2; ++a)
#pragma unroll
                for (int q = 0; q < 4; ++q) {
                    acc[a][q][0] = 0.f; acc[a][q][1] = 0.f;
                    acc[a][q][2] = 0.f; acc[a][q][3] = 0.f;
                }

            // warp-local consume: cascade wait_group orders this warp's slices
            for (int c = 0; c < nchunk; ++c) {
                cp_wait_n(nchunk - 1 - c);
                const uint32_t vb = vsm_u + c * VBUF_BYTES + b_lane;
#pragma unroll
                for (int i = 0; i < 2; ++i) {
                    const uint32_t kb = vb + (uint32_t)((w * 2 + i) * 16) * (uint32_t)VROWB;
                    uint32_t bh[8];
                    ldsm_x4t(bh[0], bh[1], bh[2], bh[3], kb);
                    ldsm_x4t(bh[4], bh[5], bh[6], bh[7], kb + 32u);
                    const int slot = c * 2 + i;
#pragma unroll
                    for (int jt = 0; jt < 2; ++jt) {
                        const uint32_t* Ah = &A[(slot * 2 + jt) * 8];
                        const uint32_t* Al = Ah + 4;
#pragma unroll
                        for (int q = 0; q < 4; ++q) {
                            const uint32_t q0 = bh[(q >> 1) * 4 + (q & 1) * 2];
                            const uint32_t q1 = bh[(q >> 1) * 4 + (q & 1) * 2 + 1];
                            mma_f16(acc[jt][q], Ah[0], Ah[1], Ah[2], Ah[3], q0, q1);
                            mma_f16(acc[jt][q], Al[0], Al[1], Al[2], Al[3], q0, q1);
                        }
                    }
                }
            }

            // ---- cross-warp K reduction ----
            {
                float* rw = redf + w * (JT * RS);
#pragma unroll
                for (int jt = 0; jt < 2; ++jt)
#pragma unroll
                    for (int q = 0; q < 4; ++q) {
                        const int b = q * 8 + tig * 2;
                        *(float2*)&rw[(jt * 16 + g) * RS + b] =
                            make_float2(acc[jt][q][0], acc[jt][q][1]);
                        *(float2*)&rw[(jt * 16 + g + 8) * RS + b] =
                            make_float2(acc[jt][q][2], acc[jt][q][3]);
                    }
            }
            __syncthreads();

            float4 sum = make_float4(bias_j, bias_j, bias_j, bias_j);
#pragma unroll
            for (int ww = 0; ww < 8; ++ww) {
                float4 v = *(const float4*)&redf[ww * (JT * RS) + jj * RS + b0e];
                sum.x += v.x; sum.y += v.y; sum.z += v.z; sum.w += v.w;
            }
            const float o0 = tanhf(sum.x), o1 = tanhf(sum.y);
            const float o2 = tanhf(sum.z), o3 = tanhf(sum.w);

            const int np = (s + 1) & 3;
            const int jg = j0 + jj;
            const int bg = b0c + b0e;
            const __half2 p01 = __floats2half2_rn(o0, o1);
            const __half2 p23 = __floats2half2_rn(o2, o3);
            *(uint2*)&g_h2[cell][np][jg][bg] =
                make_uint2(*(const uint32_t*)&p01, *(const uint32_t*)&p23);

            if (cell == 2 && t == TT - 1) {
                const uint16_t* shp = &g_h2[3][par][jg][bg];
#pragma unroll
                for (int q = 0; q < 4; ++q) {
                    float skip = __half2float(__ushort_as_half(__ldcg(&shp[q])));
                    const float ov = (q == 0) ? o0 : (q == 1) ? o1 : (q == 2) ? o2 : o3;
                    dout[(bg + q) * HH + jg] = ov + skip;
                }
            }
        }

        // ---- arrive: publish iteration completion on own group counter ----
        __syncthreads();                     // all h writes done
        if (tid == 0) {
            unsigned old;
            asm volatile("atom.add.release.gpu.u32 %0, [%1], 1;"
                         : "=r"(old) : "l"(cself) : "memory");
        }
    }
}

// ---------------- launch ------------------------------------------------------
extern "C" void kernel_launch(void* const* d_in, const int* in_sizes, int n_in,
                              void* d_out, int out_size) {
    (void)in_sizes; (void)n_in; (void)out_size;

    Params P;
    for (int i = 0; i < 20; ++i) P.p[i] = (const float*)d_in[i];

    cudaFuncSetAttribute(rec_kernel,
                         cudaFuncAttributeMaxDynamicSharedMemorySize, SMEM_TOTAL);

    init_kernel<<<128, 256>>>();
    prep_kernel<<<512, 256>>>(P);
    xconv_kernel<<<512, 256>>>((const float*)d_in[0]);
    rec_kernel<<<NCTA, 256, SMEM_TOTAL>>>((float*)d_out);
}